// round 8
// baseline (speedup 1.0000x reference)
#include <cuda_runtime.h>
#include <cuda_bf16.h>
#include <math.h>
#include <stddef.h>
#include <stdint.h>

#define BB 4
#define CC 256
#define NN 4096

typedef __nv_bfloat16 bf16;

// ---------------------------------------------------------------------------
// Scratch (__device__ globals; no allocation allowed)
// ---------------------------------------------------------------------------
__device__ __align__(16) bf16 g_xqt_h[(size_t)BB * NN * CC];  // x_q^T  [b][n][c]
__device__ __align__(16) bf16 g_xqt_l[(size_t)BB * NN * CC];
__device__ __align__(16) bf16 g_xkt_h[(size_t)BB * NN * CC];  // x_kv^T [b][n][c]
__device__ __align__(16) bf16 g_xkt_l[(size_t)BB * NN * CC];
__device__ __align__(16) bf16 g_w_h[5 * CC * CC];             // Wq,Wk,Wv,W1,W2 split
__device__ __align__(16) bf16 g_w_l[5 * CC * CC];
__device__ __align__(16) bf16 g_qt_h[(size_t)BB * NN * CC];   // q^T [b][n][c]
__device__ __align__(16) bf16 g_qt_l[(size_t)BB * NN * CC];
__device__ __align__(16) bf16 g_kt_h[(size_t)BB * NN * CC];   // k^T [b][m][c]
__device__ __align__(16) bf16 g_kt_l[(size_t)BB * NN * CC];
__device__ __align__(16) bf16 g_v_h[(size_t)BB * CC * NN];    // v   [b][c][m]
__device__ __align__(16) bf16 g_v_l[(size_t)BB * CC * NN];
__device__ __align__(16) float g_s[(size_t)BB * NN * NN];     // scores fp32 (256MB)
__device__ __align__(16) bf16 g_ah[(size_t)BB * NN * NN];     // attn hi [b][n][m]
__device__ __align__(16) bf16 g_al[(size_t)BB * NN * NN];
__device__ __align__(16) bf16 g_avt_h[(size_t)BB * NN * CC];  // av^T [b][n][c]
__device__ __align__(16) bf16 g_avt_l[(size_t)BB * NN * CC];
__device__ __align__(16) bf16 g_ht_h[(size_t)BB * NN * CC];   // hid^T [b][n][c]
__device__ __align__(16) bf16 g_ht_l[(size_t)BB * NN * CC];

// ---------------------------------------------------------------------------
// helpers
// ---------------------------------------------------------------------------
__device__ __forceinline__ void split_bf16(float f, unsigned short& h, unsigned short& l) {
    bf16 hb = __float2bfloat16(f);
    float r = f - __bfloat162float(hb);
    bf16 lb = __float2bfloat16(r);
    h = __bfloat16_as_ushort(hb);
    l = __bfloat16_as_ushort(lb);
}

__device__ __forceinline__ void mma16816(float c[4],
                                         const uint32_t a[4],
                                         uint32_t b0, uint32_t b1) {
    asm volatile(
        "mma.sync.aligned.m16n8k16.row.col.f32.bf16.bf16.f32 "
        "{%0,%1,%2,%3}, {%4,%5,%6,%7}, {%8,%9}, {%0,%1,%2,%3};"
        : "+f"(c[0]), "+f"(c[1]), "+f"(c[2]), "+f"(c[3])
        : "r"(a[0]), "r"(a[1]), "r"(a[2]), "r"(a[3]), "r"(b0), "r"(b1));
}

__device__ __forceinline__ void ldsm4(uint32_t r[4], uint32_t addr) {
    asm volatile("ldmatrix.sync.aligned.m8n8.x4.shared.b16 {%0,%1,%2,%3}, [%4];"
                 : "=r"(r[0]), "=r"(r[1]), "=r"(r[2]), "=r"(r[3]) : "r"(addr));
}

__device__ __forceinline__ void cp16(uint32_t dst, const void* src) {
    asm volatile("cp.async.cg.shared.global [%0], [%1], 16;" :: "r"(dst), "l"(src));
}

// ---------------------------------------------------------------------------
// split-transpose: X [b][c][n] fp32 -> T [b][n][c] bf16 hi/lo
// ---------------------------------------------------------------------------
__global__ void split_transpose(const float* __restrict__ X,
                                unsigned short* __restrict__ Th,
                                unsigned short* __restrict__ Tl) {
    __shared__ float tile[32][33];
    const int b  = blockIdx.z;
    const int c0 = blockIdx.y * 32;
    const int n0 = blockIdx.x * 32;
    const float* Xb = X + (size_t)b * CC * NN;
    const int tx = threadIdx.x, ty = threadIdx.y;

#pragma unroll
    for (int i = 0; i < 4; i++)
        tile[ty + 8 * i][tx] = Xb[(size_t)(c0 + ty + 8 * i) * NN + n0 + tx];
    __syncthreads();

    unsigned short* Thb = Th + (size_t)b * NN * CC;
    unsigned short* Tlb = Tl + (size_t)b * NN * CC;
#pragma unroll
    for (int i = 0; i < 4; i++) {
        float v = tile[tx][ty + 8 * i];
        unsigned short h, l;
        split_bf16(v, h, l);
        size_t off = (size_t)(n0 + ty + 8 * i) * CC + c0 + tx;
        Thb[off] = h;
        Tlb[off] = l;
    }
}

// ---------------------------------------------------------------------------
// plain split: W fp32 -> hi/lo
// ---------------------------------------------------------------------------
__global__ void split_mat(const float* __restrict__ W,
                          unsigned short* __restrict__ Wh,
                          unsigned short* __restrict__ Wl, int n) {
    int i = blockIdx.x * blockDim.x + threadIdx.x;
    if (i < n) {
        unsigned short h, l;
        split_bf16(W[i], h, l);
        Wh[i] = h;
        Wl[i] = l;
    }
}

// ---------------------------------------------------------------------------
// HMMA GEMM (small, block 128x128, warp 64x32) — proven R6 path, used for the
// five K=256 projections.
// ---------------------------------------------------------------------------
#define BKC 32
#define SPITCH 40
#define ST_ELEMS (2 * 128 * SPITCH)
#define ST_BYTES (ST_ELEMS * 2)
#define B_OFF_BYTES (2 * ST_BYTES)
#define SMEM_TOTAL_BYTES (4 * ST_BYTES)

extern __shared__ __align__(16) bf16 smem_mma[];

template <int EPI, bool RELU>
__global__ __launch_bounds__(256)
void mma_gemm(const bf16* __restrict__ Ah, const bf16* __restrict__ Al,
              size_t sAb, int lda,
              const bf16* __restrict__ Bh, const bf16* __restrict__ Bl,
              size_t sBb, int ldb,
              float* __restrict__ Cf,
              unsigned short* __restrict__ Ch, unsigned short* __restrict__ Cl,
              size_t sCb, int ldc,
              const float* __restrict__ bias, int Ktot) {
    const int b    = blockIdx.z;
    const int row0 = blockIdx.y * 128;
    const int col0 = blockIdx.x * 128;
    Ah += (size_t)b * sAb;  Al += (size_t)b * sAb;
    Bh += (size_t)b * sBb;  Bl += (size_t)b * sBb;

    const int tid  = threadIdx.x;
    const int w    = tid >> 5, lane = tid & 31;
    const int g    = lane >> 2, tig = lane & 3;
    const int wm   = (w & 1) * 64;
    const int wn   = (w >> 1) * 32;

    uint32_t smem_u32;
    asm("{ .reg .u64 t; cvta.to.shared.u64 t, %1; cvt.u32.u64 %0, t; }"
        : "=r"(smem_u32) : "l"(smem_mma));

    auto issue_copy = [&](int k0, int st) {
#pragma unroll
        for (int i = 0; i < 8; i++) {
            int idx = tid + i * 256;
            int ab = idx >> 10;
            int h  = (idx >> 9) & 1;
            int r  = (idx >> 2) & 127;
            int ch = idx & 3;
            uint32_t dst = smem_u32 + st * ST_BYTES +
                           (uint32_t)(((h * 128 + r) * SPITCH + ch * 8) * 2);
            const bf16* src;
            if (ab == 0) {
                src = (h ? Al : Ah) + (size_t)(row0 + r) * lda + k0 + ch * 8;
            } else {
                dst += B_OFF_BYTES;
                src = (h ? Bl : Bh) + (size_t)(col0 + r) * ldb + k0 + ch * 8;
            }
            cp16(dst, src);
        }
        asm volatile("cp.async.commit_group;" ::: "memory");
    };

    float acc[4][4][4] = {};

    issue_copy(0, 0);
    asm volatile("cp.async.wait_group 0;" ::: "memory");
    __syncthreads();

    const int lr = lane & 15;
    const int lc = (lane >> 4) * 8;

    const int nstep = Ktot / BKC;
    for (int s = 0; s < nstep; s++) {
        int st = s & 1;
        bool more = (s + 1) < nstep;
        if (more) issue_copy((s + 1) * BKC, st ^ 1);

        uint32_t aBase = smem_u32 + st * ST_BYTES;
        uint32_t bBase = aBase + B_OFF_BYTES;

#pragma unroll
        for (int ks = 0; ks < BKC; ks += 16) {
            uint32_t fA[2][4][4];
            uint32_t fB[2][2][4];
#pragma unroll
            for (int h = 0; h < 2; h++) {
#pragma unroll
                for (int ar = 0; ar < 4; ar++) {
                    uint32_t addr = aBase +
                        (uint32_t)(((h * 128 + wm + ar * 16 + lr) * SPITCH + ks + lc) * 2);
                    ldsm4(fA[h][ar], addr);
                }
#pragma unroll
                for (int bp = 0; bp < 2; bp++) {
                    uint32_t addr = bBase +
                        (uint32_t)(((h * 128 + wn + bp * 16 + lr) * SPITCH + ks + lc) * 2);
                    ldsm4(fB[h][bp], addr);
                }
            }
#pragma unroll
            for (int ar = 0; ar < 4; ar++)
#pragma unroll
            for (int bn = 0; bn < 4; bn++) {
                int bp = bn >> 1, sel = bn & 1;
                uint32_t b0h = fB[0][bp][sel], b1h = fB[0][bp][2 + sel];
                uint32_t b0l = fB[1][bp][sel], b1l = fB[1][bp][2 + sel];
                mma16816(acc[ar][bn], fA[0][ar], b0h, b1h);
                mma16816(acc[ar][bn], fA[0][ar], b0l, b1l);
                mma16816(acc[ar][bn], fA[1][ar], b0h, b1h);
            }
        }
        if (more) {
            asm volatile("cp.async.wait_group 0;" ::: "memory");
            __syncthreads();
        }
    }

#pragma unroll
    for (int ar = 0; ar < 4; ar++) {
        int r0 = row0 + wm + ar * 16 + g;
        float bs0 = bias ? bias[r0]     : 0.0f;
        float bs8 = bias ? bias[r0 + 8] : 0.0f;
#pragma unroll
        for (int bn = 0; bn < 4; bn++) {
            int c0 = col0 + wn + bn * 8 + 2 * tig;
            float v0 = acc[ar][bn][0] + bs0;
            float v1 = acc[ar][bn][1] + bs0;
            float v2 = acc[ar][bn][2] + bs8;
            float v3 = acc[ar][bn][3] + bs8;
            if (RELU) {
                v0 = fmaxf(v0, 0.f); v1 = fmaxf(v1, 0.f);
                v2 = fmaxf(v2, 0.f); v3 = fmaxf(v3, 0.f);
            }
            if (EPI == 0) {
                float* C = Cf + (size_t)b * sCb;
                *(float2*)&C[(size_t)r0 * ldc + c0]       = make_float2(v0, v1);
                *(float2*)&C[(size_t)(r0 + 8) * ldc + c0] = make_float2(v2, v3);
            } else if (EPI == 1) {
                unsigned short* Hc = Ch + (size_t)b * sCb;
                unsigned short* Lc = Cl + (size_t)b * sCb;
                unsigned short h0, l0, h1, l1, h2, l2, h3, l3;
                split_bf16(v0, h0, l0); split_bf16(v1, h1, l1);
                split_bf16(v2, h2, l2); split_bf16(v3, h3, l3);
                *(uint32_t*)&Hc[(size_t)r0 * ldc + c0]       = (uint32_t)h0 | ((uint32_t)h1 << 16);
                *(uint32_t*)&Lc[(size_t)r0 * ldc + c0]       = (uint32_t)l0 | ((uint32_t)l1 << 16);
                *(uint32_t*)&Hc[(size_t)(r0 + 8) * ldc + c0] = (uint32_t)h2 | ((uint32_t)h3 << 16);
                *(uint32_t*)&Lc[(size_t)(r0 + 8) * ldc + c0] = (uint32_t)l2 | ((uint32_t)l3 << 16);
            } else {
                unsigned short* Hc = Ch + (size_t)b * sCb;
                unsigned short* Lc = Cl + (size_t)b * sCb;
                unsigned short h, l;
                split_bf16(v0, h, l);
                Hc[(size_t)c0 * ldc + r0] = h;           Lc[(size_t)c0 * ldc + r0] = l;
                split_bf16(v1, h, l);
                Hc[(size_t)(c0 + 1) * ldc + r0] = h;     Lc[(size_t)(c0 + 1) * ldc + r0] = l;
                split_bf16(v2, h, l);
                Hc[(size_t)c0 * ldc + r0 + 8] = h;       Lc[(size_t)c0 * ldc + r0 + 8] = l;
                split_bf16(v3, h, l);
                Hc[(size_t)(c0 + 1) * ldc + r0 + 8] = h; Lc[(size_t)(c0 + 1) * ldc + r0 + 8] = l;
            }
        }
    }
}

// ---------------------------------------------------------------------------
// HMMA GEMM (big): block 128x256, warp tile 64x64, 8 warps (2x4).
// Halves smem-read bytes per MMA vs the small kernel -> higher tensor util.
// EPI 0: fp32 [row][col]; EPI 2: transposed split bf16 [col][row].
// ---------------------------------------------------------------------------
#define A_ST2 (2 * 128 * SPITCH * 2)          // 20480 bytes per stage (A hl)
#define B_ST2 (2 * 256 * SPITCH * 2)          // 40960 bytes per stage (B hl)
#define STAGE2 (A_ST2 + B_ST2)                // 61440
#define SMEM_BIG_BYTES (2 * STAGE2)           // 122880

template <int EPI>
__global__ __launch_bounds__(256)
void mma_gemm_big(const bf16* __restrict__ Ah, const bf16* __restrict__ Al,
                  size_t sAb, int lda,
                  const bf16* __restrict__ Bh, const bf16* __restrict__ Bl,
                  size_t sBb, int ldb,
                  float* __restrict__ Cf,
                  unsigned short* __restrict__ Ch, unsigned short* __restrict__ Cl,
                  size_t sCb, int ldc, int Ktot) {
    const int b    = blockIdx.z;
    const int row0 = blockIdx.y * 128;
    const int col0 = blockIdx.x * 256;
    Ah += (size_t)b * sAb;  Al += (size_t)b * sAb;
    Bh += (size_t)b * sBb;  Bl += (size_t)b * sBb;

    const int tid  = threadIdx.x;
    const int w    = tid >> 5, lane = tid & 31;
    const int g    = lane >> 2, tig = lane & 3;
    const int wm   = (w & 1) * 64;      // warp row offset (2 rows of warps)
    const int wn   = (w >> 1) * 64;     // warp col offset (4 cols of warps)

    uint32_t smem_u32;
    asm("{ .reg .u64 t; cvta.to.shared.u64 t, %1; cvt.u32.u64 %0, t; }"
        : "=r"(smem_u32) : "l"(smem_mma));

    // one stage = A(2hl x 128 rows) + B(2hl x 256 rows), 4 chunks of 16B per row
    // total 3072 chunks; 12 per thread.
    auto issue_copy = [&](int k0, int st) {
        uint32_t base = smem_u32 + st * STAGE2;
#pragma unroll
        for (int i = 0; i < 12; i++) {
            int idx = tid + i * 256;
            uint32_t dst;
            const bf16* src;
            if (idx < 1024) {  // A: h=(idx>>9), r=(idx>>2)&127, ch=idx&3
                int h  = (idx >> 9) & 1;
                int r  = (idx >> 2) & 127;
                int ch = idx & 3;
                dst = base + (uint32_t)(((h * 128 + r) * SPITCH + ch * 8) * 2);
                src = (h ? Al : Ah) + (size_t)(row0 + r) * lda + k0 + ch * 8;
            } else {           // B: h=(idx2>>10), r=(idx2>>2)&255, ch=idx2&3
                int idx2 = idx - 1024;
                int h  = (idx2 >> 10) & 1;
                int r  = (idx2 >> 2) & 255;
                int ch = idx2 & 3;
                dst = base + A_ST2 + (uint32_t)(((h * 256 + r) * SPITCH + ch * 8) * 2);
                src = (h ? Bl : Bh) + (size_t)(col0 + r) * ldb + k0 + ch * 8;
            }
            cp16(dst, src);
        }
        asm volatile("cp.async.commit_group;" ::: "memory");
    };

    float acc[4][8][4] = {};

    issue_copy(0, 0);
    asm volatile("cp.async.wait_group 0;" ::: "memory");
    __syncthreads();

    const int lr = lane & 15;
    const int lc = (lane >> 4) * 8;

    const int nstep = Ktot / BKC;
    for (int s = 0; s < nstep; s++) {
        int st = s & 1;
        bool more = (s + 1) < nstep;
        if (more) issue_copy((s + 1) * BKC, st ^ 1);

        uint32_t aBase = smem_u32 + st * STAGE2;
        uint32_t bBase = aBase + A_ST2;

#pragma unroll
        for (int ks = 0; ks < BKC; ks += 16) {
            uint32_t fA[2][4][4];
#pragma unroll
            for (int h = 0; h < 2; h++)
#pragma unroll
            for (int ar = 0; ar < 4; ar++) {
                uint32_t addr = aBase +
                    (uint32_t)(((h * 128 + wm + ar * 16 + lr) * SPITCH + ks + lc) * 2);
                ldsm4(fA[h][ar], addr);
            }
#pragma unroll
            for (int bp = 0; bp < 4; bp++) {
                uint32_t fBh[4], fBl[4];
                uint32_t ah_ = bBase +
                    (uint32_t)(((0 * 256 + wn + bp * 16 + lr) * SPITCH + ks + lc) * 2);
                uint32_t al_ = bBase +
                    (uint32_t)(((1 * 256 + wn + bp * 16 + lr) * SPITCH + ks + lc) * 2);
                ldsm4(fBh, ah_);
                ldsm4(fBl, al_);
#pragma unroll
                for (int sel = 0; sel < 2; sel++) {
                    int bn = bp * 2 + sel;
                    uint32_t b0h = fBh[sel], b1h = fBh[2 + sel];
                    uint32_t b0l = fBl[sel], b1l = fBl[2 + sel];
#pragma unroll
                    for (int ar = 0; ar < 4; ar++) {
                        mma16816(acc[ar][bn], fA[0][ar], b0h, b1h);
                        mma16816(acc[ar][bn], fA[0][ar], b0l, b1l);
                        mma16816(acc[ar][bn], fA[1][ar], b0h, b1h);
                    }
                }
            }
        }
        if (more) {
            asm volatile("cp.async.wait_group 0;" ::: "memory");
            __syncthreads();
        }
    }

#pragma unroll
    for (int ar = 0; ar < 4; ar++) {
        int r0 = row0 + wm + ar * 16 + g;
#pragma unroll
        for (int bn = 0; bn < 8; bn++) {
            int c0 = col0 + wn + bn * 8 + 2 * tig;
            float v0 = acc[ar][bn][0];
            float v1 = acc[ar][bn][1];
            float v2 = acc[ar][bn][2];
            float v3 = acc[ar][bn][3];
            if (EPI == 0) {
                float* C = Cf + (size_t)b * sCb;
                *(float2*)&C[(size_t)r0 * ldc + c0]       = make_float2(v0, v1);
                *(float2*)&C[(size_t)(r0 + 8) * ldc + c0] = make_float2(v2, v3);
            } else {
                unsigned short* Hc = Ch + (size_t)b * sCb;
                unsigned short* Lc = Cl + (size_t)b * sCb;
                unsigned short h, l;
                split_bf16(v0, h, l);
                Hc[(size_t)c0 * ldc + r0] = h;           Lc[(size_t)c0 * ldc + r0] = l;
                split_bf16(v1, h, l);
                Hc[(size_t)(c0 + 1) * ldc + r0] = h;     Lc[(size_t)(c0 + 1) * ldc + r0] = l;
                split_bf16(v2, h, l);
                Hc[(size_t)c0 * ldc + r0 + 8] = h;       Lc[(size_t)c0 * ldc + r0 + 8] = l;
                split_bf16(v3, h, l);
                Hc[(size_t)(c0 + 1) * ldc + r0 + 8] = h; Lc[(size_t)(c0 + 1) * ldc + r0 + 8] = l;
            }
        }
    }
}

// ---------------------------------------------------------------------------
// Row softmax; reads fp32 scores, writes split-bf16 attention.
// ---------------------------------------------------------------------------
__global__ void softmax_split(const float* __restrict__ S,
                              bf16* __restrict__ Ah, bf16* __restrict__ Al) {
    __shared__ float red[256];
    const float4* p = (const float4*)(S + (size_t)blockIdx.x * NN);
    const int tid = threadIdx.x;

    float4 r[4];
    float mx = -INFINITY;
#pragma unroll
    for (int i = 0; i < 4; i++) {
        r[i] = p[tid + i * 256];
        mx = fmaxf(mx, fmaxf(fmaxf(r[i].x, r[i].y), fmaxf(r[i].z, r[i].w)));
    }
    red[tid] = mx;
    __syncthreads();
    for (int s = 128; s > 0; s >>= 1) {
        if (tid < s) red[tid] = fmaxf(red[tid], red[tid + s]);
        __syncthreads();
    }
    mx = red[0];
    __syncthreads();

    float sum = 0.0f;
#pragma unroll
    for (int i = 0; i < 4; i++) {
        r[i].x = __expf(r[i].x - mx); r[i].y = __expf(r[i].y - mx);
        r[i].z = __expf(r[i].z - mx); r[i].w = __expf(r[i].w - mx);
        sum += r[i].x + r[i].y + r[i].z + r[i].w;
    }
    red[tid] = sum;
    __syncthreads();
    for (int s = 128; s > 0; s >>= 1) {
        if (tid < s) red[tid] += red[tid + s];
        __syncthreads();
    }
    float inv = 1.0f / red[0];

    bf16* ah = Ah + (size_t)blockIdx.x * NN;
    bf16* al = Al + (size_t)blockIdx.x * NN;
#pragma unroll
    for (int i = 0; i < 4; i++) {
        float v[4] = {r[i].x * inv, r[i].y * inv, r[i].z * inv, r[i].w * inv};
        unsigned short hs[4], ls[4];
#pragma unroll
        for (int c = 0; c < 4; c++) split_bf16(v[c], hs[c], ls[c]);
        uint2 uh = make_uint2((uint32_t)hs[0] | ((uint32_t)hs[1] << 16),
                              (uint32_t)hs[2] | ((uint32_t)hs[3] << 16));
        uint2 ul = make_uint2((uint32_t)ls[0] | ((uint32_t)ls[1] << 16),
                              (uint32_t)ls[2] | ((uint32_t)ls[3] << 16));
        size_t off = (size_t)(tid + i * 256) * 4;
        *(uint2*)&ah[off] = uh;
        *(uint2*)&al[off] = ul;
    }
}

// ---------------------------------------------------------------------------
extern "C" void kernel_launch(void* const* d_in, const int* in_sizes, int n_in,
                              void* d_out, int out_size) {
    const float* x_q  = (const float*)d_in[0];
    const float* x_kv = (const float*)d_in[1];
    const float* Wq = (const float*)d_in[2];
    const float* bq = (const float*)d_in[3];
    const float* Wk = (const float*)d_in[4];
    const float* bk = (const float*)d_in[5];
    const float* Wv = (const float*)d_in[6];
    const float* bv = (const float*)d_in[7];
    const float* W1 = (const float*)d_in[8];
    const float* b1 = (const float*)d_in[9];
    const float* W2 = (const float*)d_in[10];
    const float* b2 = (const float*)d_in[11];
    float* out = (float*)d_out;

    bf16 *xqt_h, *xqt_l, *xkt_h, *xkt_l, *w_h, *w_l;
    bf16 *qt_h, *qt_l, *kt_h, *kt_l, *v_h, *v_l;
    bf16 *ah, *al, *avt_h, *avt_l, *ht_h, *ht_l;
    float* ps;
    cudaGetSymbolAddress((void**)&xqt_h, g_xqt_h);
    cudaGetSymbolAddress((void**)&xqt_l, g_xqt_l);
    cudaGetSymbolAddress((void**)&xkt_h, g_xkt_h);
    cudaGetSymbolAddress((void**)&xkt_l, g_xkt_l);
    cudaGetSymbolAddress((void**)&w_h,   g_w_h);
    cudaGetSymbolAddress((void**)&w_l,   g_w_l);
    cudaGetSymbolAddress((void**)&qt_h,  g_qt_h);
    cudaGetSymbolAddress((void**)&qt_l,  g_qt_l);
    cudaGetSymbolAddress((void**)&kt_h,  g_kt_h);
    cudaGetSymbolAddress((void**)&kt_l,  g_kt_l);
    cudaGetSymbolAddress((void**)&v_h,   g_v_h);
    cudaGetSymbolAddress((void**)&v_l,   g_v_l);
    cudaGetSymbolAddress((void**)&ps,    g_s);
    cudaGetSymbolAddress((void**)&ah,    g_ah);
    cudaGetSymbolAddress((void**)&al,    g_al);
    cudaGetSymbolAddress((void**)&avt_h, g_avt_h);
    cudaGetSymbolAddress((void**)&avt_l, g_avt_l);
    cudaGetSymbolAddress((void**)&ht_h,  g_ht_h);
    cudaGetSymbolAddress((void**)&ht_l,  g_ht_l);

    cudaFuncSetAttribute(mma_gemm<0, false>, cudaFuncAttributeMaxDynamicSharedMemorySize, SMEM_TOTAL_BYTES);
    cudaFuncSetAttribute(mma_gemm<1, false>, cudaFuncAttributeMaxDynamicSharedMemorySize, SMEM_TOTAL_BYTES);
    cudaFuncSetAttribute(mma_gemm<2, false>, cudaFuncAttributeMaxDynamicSharedMemorySize, SMEM_TOTAL_BYTES);
    cudaFuncSetAttribute(mma_gemm<2, true>,  cudaFuncAttributeMaxDynamicSharedMemorySize, SMEM_TOTAL_BYTES);
    cudaFuncSetAttribute(mma_gemm_big<0>, cudaFuncAttributeMaxDynamicSharedMemorySize, SMEM_BIG_BYTES);
    cudaFuncSetAttribute(mma_gemm_big<2>, cudaFuncAttributeMaxDynamicSharedMemorySize, SMEM_BIG_BYTES);

    const int WSZ = CC * CC;

    dim3 tb(256);
    dim3 gT(NN / 32, CC / 32, BB);
    dim3 gProj(NN / 128, CC / 128, BB);       // (32, 2, 4)
    dim3 gScore(NN / 256, NN / 128, BB);      // (16, 32, 4)
    dim3 gAV(NN / 256, CC / 128, BB);         // (16, 2, 4)

    // 1. input split-transpose + weight splits
    split_transpose<<<gT, dim3(32, 8)>>>(x_q,  (unsigned short*)xqt_h, (unsigned short*)xqt_l);
    split_transpose<<<gT, dim3(32, 8)>>>(x_kv, (unsigned short*)xkt_h, (unsigned short*)xkt_l);
    split_mat<<<WSZ / 256, 256>>>(Wq, (unsigned short*)(w_h + 0 * WSZ), (unsigned short*)(w_l + 0 * WSZ), WSZ);
    split_mat<<<WSZ / 256, 256>>>(Wk, (unsigned short*)(w_h + 1 * WSZ), (unsigned short*)(w_l + 1 * WSZ), WSZ);
    split_mat<<<WSZ / 256, 256>>>(Wv, (unsigned short*)(w_h + 2 * WSZ), (unsigned short*)(w_l + 2 * WSZ), WSZ);
    split_mat<<<WSZ / 256, 256>>>(W1, (unsigned short*)(w_h + 3 * WSZ), (unsigned short*)(w_l + 3 * WSZ), WSZ);
    split_mat<<<WSZ / 256, 256>>>(W2, (unsigned short*)(w_h + 4 * WSZ), (unsigned short*)(w_l + 4 * WSZ), WSZ);

    // 2. projections (small HMMA path)
    mma_gemm<2, false><<<gProj, tb, SMEM_TOTAL_BYTES>>>(
        w_h + 0 * WSZ, w_l + 0 * WSZ, 0, CC,
        xqt_h, xqt_l, (size_t)NN * CC, CC,
        nullptr, (unsigned short*)qt_h, (unsigned short*)qt_l,
        (size_t)NN * CC, CC, bq, CC);
    mma_gemm<2, false><<<gProj, tb, SMEM_TOTAL_BYTES>>>(
        w_h + 1 * WSZ, w_l + 1 * WSZ, 0, CC,
        xkt_h, xkt_l, (size_t)NN * CC, CC,
        nullptr, (unsigned short*)kt_h, (unsigned short*)kt_l,
        (size_t)NN * CC, CC, bk, CC);
    mma_gemm<1, false><<<gProj, tb, SMEM_TOTAL_BYTES>>>(
        w_h + 2 * WSZ, w_l + 2 * WSZ, 0, CC,
        xkt_h, xkt_l, (size_t)NN * CC, CC,
        nullptr, (unsigned short*)v_h, (unsigned short*)v_l,
        (size_t)CC * NN, NN, bv, CC);

    // 3. scores S[n][m] fp32 (big HMMA)
    mma_gemm_big<0><<<gScore, tb, SMEM_BIG_BYTES>>>(
        qt_h, qt_l, (size_t)NN * CC, CC,
        kt_h, kt_l, (size_t)NN * CC, CC,
        ps, nullptr, nullptr, (size_t)NN * NN, NN, CC);

    // 4. softmax -> split attn
    softmax_split<<<BB * NN, tb>>>(ps, ah, al);

    // 5. AV (big HMMA): rows = v channels (c), cols = attn rows (n), K = m
    //    EPI2 writes av_t[n][c] directly.
    mma_gemm_big<2><<<gAV, tb, SMEM_BIG_BYTES>>>(
        v_h, v_l, (size_t)CC * NN, NN,
        ah, al, (size_t)NN * NN, NN,
        nullptr, (unsigned short*)avt_h, (unsigned short*)avt_l,
        (size_t)NN * CC, CC, NN);

    // 6. FFN1 (relu fused): hid_t[n][o]
    mma_gemm<2, true><<<gProj, tb, SMEM_TOTAL_BYTES>>>(
        w_h + 3 * WSZ, w_l + 3 * WSZ, 0, CC,
        avt_h, avt_l, (size_t)NN * CC, CC,
        nullptr, (unsigned short*)ht_h, (unsigned short*)ht_l,
        (size_t)NN * CC, CC, b1, CC);

    // 7. FFN2: fp32 out [o][n]
    mma_gemm<0, false><<<gProj, tb, SMEM_TOTAL_BYTES>>>(
        w_h + 4 * WSZ, w_l + 4 * WSZ, 0, CC,
        ht_h, ht_l, (size_t)NN * CC, CC,
        out, nullptr, nullptr, (size_t)CC * NN, NN, b2, CC);
}

// round 9
// speedup vs baseline: 1.0899x; 1.0899x over previous
#include <cuda_runtime.h>
#include <cuda_bf16.h>
#include <math.h>
#include <stddef.h>
#include <stdint.h>

#define BB 4
#define CC 256
#define NN 4096

typedef __nv_bfloat16 bf16;

// ---------------------------------------------------------------------------
// Scratch (__device__ globals; no allocation allowed)
// ---------------------------------------------------------------------------
__device__ __align__(16) bf16 g_xqt_h[(size_t)BB * NN * CC];  // x_q^T  [b][n][c]
__device__ __align__(16) bf16 g_xqt_l[(size_t)BB * NN * CC];
__device__ __align__(16) bf16 g_xkt_h[(size_t)BB * NN * CC];  // x_kv^T [b][n][c]
__device__ __align__(16) bf16 g_xkt_l[(size_t)BB * NN * CC];
__device__ __align__(16) bf16 g_w_h[5 * CC * CC];             // Wq,Wk,Wv,W1,W2 split
__device__ __align__(16) bf16 g_w_l[5 * CC * CC];
__device__ __align__(16) bf16 g_qt_h[(size_t)BB * NN * CC];   // q^T [b][n][c]
__device__ __align__(16) bf16 g_qt_l[(size_t)BB * NN * CC];
__device__ __align__(16) bf16 g_kt_h[(size_t)BB * NN * CC];   // k^T [b][m][c]
__device__ __align__(16) bf16 g_kt_l[(size_t)BB * NN * CC];
__device__ __align__(16) bf16 g_v_h[(size_t)BB * CC * NN];    // v   [b][c][m]
__device__ __align__(16) bf16 g_v_l[(size_t)BB * CC * NN];
__device__ __align__(16) bf16 g_ah[(size_t)BB * NN * NN];     // exp(S) hi [b][n][m]
__device__ __align__(16) bf16 g_al[(size_t)BB * NN * NN];     // exp(S) lo
__device__ __align__(16) float g_z[(size_t)BB * NN];          // row sums of exp(S)
__device__ __align__(16) bf16 g_avt_h[(size_t)BB * NN * CC];  // av^T [b][n][c]
__device__ __align__(16) bf16 g_avt_l[(size_t)BB * NN * CC];
__device__ __align__(16) bf16 g_ht_h[(size_t)BB * NN * CC];   // hid^T [b][n][c]
__device__ __align__(16) bf16 g_ht_l[(size_t)BB * NN * CC];

// ---------------------------------------------------------------------------
// helpers
// ---------------------------------------------------------------------------
__device__ __forceinline__ void split_bf16(float f, unsigned short& h, unsigned short& l) {
    bf16 hb = __float2bfloat16(f);
    float r = f - __bfloat162float(hb);
    bf16 lb = __float2bfloat16(r);
    h = __bfloat16_as_ushort(hb);
    l = __bfloat16_as_ushort(lb);
}

__device__ __forceinline__ void mma16816(float c[4],
                                         const uint32_t a[4],
                                         uint32_t b0, uint32_t b1) {
    asm volatile(
        "mma.sync.aligned.m16n8k16.row.col.f32.bf16.bf16.f32 "
        "{%0,%1,%2,%3}, {%4,%5,%6,%7}, {%8,%9}, {%0,%1,%2,%3};"
        : "+f"(c[0]), "+f"(c[1]), "+f"(c[2]), "+f"(c[3])
        : "r"(a[0]), "r"(a[1]), "r"(a[2]), "r"(a[3]), "r"(b0), "r"(b1));
}

__device__ __forceinline__ void ldsm4(uint32_t r[4], uint32_t addr) {
    asm volatile("ldmatrix.sync.aligned.m8n8.x4.shared.b16 {%0,%1,%2,%3}, [%4];"
                 : "=r"(r[0]), "=r"(r[1]), "=r"(r[2]), "=r"(r[3]) : "r"(addr));
}

__device__ __forceinline__ void cp16(uint32_t dst, const void* src) {
    asm volatile("cp.async.cg.shared.global [%0], [%1], 16;" :: "r"(dst), "l"(src));
}

// ---------------------------------------------------------------------------
// merged split-transpose: z<BB -> x_q, else x_kv.  [b][c][n] f32 -> [b][n][c] split
// ---------------------------------------------------------------------------
__global__ void split_transpose2(const float* __restrict__ Xq,
                                 const float* __restrict__ Xkv,
                                 unsigned short* __restrict__ Tqh,
                                 unsigned short* __restrict__ Tql,
                                 unsigned short* __restrict__ Tkh,
                                 unsigned short* __restrict__ Tkl) {
    __shared__ float tile[32][33];
    const int z  = blockIdx.z;
    const int b  = (z < BB) ? z : z - BB;
    const float* X = (z < BB) ? Xq : Xkv;
    unsigned short* Th = ((z < BB) ? Tqh : Tkh) + (size_t)b * NN * CC;
    unsigned short* Tl = ((z < BB) ? Tql : Tkl) + (size_t)b * NN * CC;

    const int c0 = blockIdx.y * 32;
    const int n0 = blockIdx.x * 32;
    const float* Xb = X + (size_t)b * CC * NN;
    const int tx = threadIdx.x, ty = threadIdx.y;

#pragma unroll
    for (int i = 0; i < 4; i++)
        tile[ty + 8 * i][tx] = Xb[(size_t)(c0 + ty + 8 * i) * NN + n0 + tx];
    __syncthreads();

#pragma unroll
    for (int i = 0; i < 4; i++) {
        float v = tile[tx][ty + 8 * i];
        unsigned short h, l;
        split_bf16(v, h, l);
        size_t off = (size_t)(n0 + ty + 8 * i) * CC + c0 + tx;
        Th[off] = h;
        Tl[off] = l;
    }
}

// ---------------------------------------------------------------------------
// merged weight split: 5 matrices of CC*CC each into contiguous hi/lo buffers
// ---------------------------------------------------------------------------
__global__ void split_all(const float* __restrict__ W0, const float* __restrict__ W1,
                          const float* __restrict__ W2, const float* __restrict__ W3,
                          const float* __restrict__ W4,
                          unsigned short* __restrict__ Wh,
                          unsigned short* __restrict__ Wl) {
    int i = blockIdx.x * blockDim.x + threadIdx.x;
    int which = i >> 16;           // CC*CC = 65536
    int off   = i & 65535;
    const float* src = (which == 0) ? W0 : (which == 1) ? W1 :
                       (which == 2) ? W2 : (which == 3) ? W3 : W4;
    unsigned short h, l;
    split_bf16(src[off], h, l);
    Wh[i] = h;
    Wl[i] = l;
}

__global__ void zero_z(float* __restrict__ Z) {
    Z[blockIdx.x * 256 + threadIdx.x] = 0.0f;
}

// ---------------------------------------------------------------------------
// HMMA GEMM, block 128x128, warp 64x32, 3-term bf16 split.
// EPI 0: fp32 [row][col] (+bias, opt relu)
// EPI 1: split bf16 natural [row][col] (+bias)
// EPI 2: split bf16 transposed [col][row] (+bias, opt relu, opt 1/Z[col] scale)
// EPI 3: exp() -> split bf16 [row][col] + atomic row sums into Zp
// ---------------------------------------------------------------------------
#define BKC 32
#define SPITCH 40
#define ST_ELEMS (2 * 128 * SPITCH)
#define ST_BYTES (ST_ELEMS * 2)
#define B_OFF_BYTES (2 * ST_BYTES)
#define SMEM_TOTAL_BYTES (4 * ST_BYTES)

extern __shared__ __align__(16) bf16 smem_mma[];

template <int EPI, bool RELU>
__global__ __launch_bounds__(256)
void mma_gemm(const bf16* __restrict__ Ah, const bf16* __restrict__ Al,
              size_t sAb, int lda,
              const bf16* __restrict__ Bh, const bf16* __restrict__ Bl,
              size_t sBb, int ldb,
              float* __restrict__ Cf,
              unsigned short* __restrict__ Ch, unsigned short* __restrict__ Cl,
              size_t sCb, int ldc,
              const float* __restrict__ bias, float* __restrict__ Zp, int Ktot) {
    const int b    = blockIdx.z;
    const int row0 = blockIdx.y * 128;
    const int col0 = blockIdx.x * 128;
    Ah += (size_t)b * sAb;  Al += (size_t)b * sAb;
    Bh += (size_t)b * sBb;  Bl += (size_t)b * sBb;

    const int tid  = threadIdx.x;
    const int w    = tid >> 5, lane = tid & 31;
    const int g    = lane >> 2, tig = lane & 3;
    const int wm   = (w & 1) * 64;
    const int wn   = (w >> 1) * 32;

    uint32_t smem_u32;
    asm("{ .reg .u64 t; cvta.to.shared.u64 t, %1; cvt.u32.u64 %0, t; }"
        : "=r"(smem_u32) : "l"(smem_mma));

    auto issue_copy = [&](int k0, int st) {
#pragma unroll
        for (int i = 0; i < 8; i++) {
            int idx = tid + i * 256;
            int ab = idx >> 10;
            int h  = (idx >> 9) & 1;
            int r  = (idx >> 2) & 127;
            int ch = idx & 3;
            uint32_t dst = smem_u32 + st * ST_BYTES +
                           (uint32_t)(((h * 128 + r) * SPITCH + ch * 8) * 2);
            const bf16* src;
            if (ab == 0) {
                src = (h ? Al : Ah) + (size_t)(row0 + r) * lda + k0 + ch * 8;
            } else {
                dst += B_OFF_BYTES;
                src = (h ? Bl : Bh) + (size_t)(col0 + r) * ldb + k0 + ch * 8;
            }
            cp16(dst, src);
        }
        asm volatile("cp.async.commit_group;" ::: "memory");
    };

    float acc[4][4][4] = {};

    issue_copy(0, 0);
    asm volatile("cp.async.wait_group 0;" ::: "memory");
    __syncthreads();

    const int lr = lane & 15;
    const int lc = (lane >> 4) * 8;

    const int nstep = Ktot / BKC;
    for (int s = 0; s < nstep; s++) {
        int st = s & 1;
        bool more = (s + 1) < nstep;
        if (more) issue_copy((s + 1) * BKC, st ^ 1);

        uint32_t aBase = smem_u32 + st * ST_BYTES;
        uint32_t bBase = aBase + B_OFF_BYTES;

#pragma unroll
        for (int ks = 0; ks < BKC; ks += 16) {
            uint32_t fA[2][4][4];
            uint32_t fB[2][2][4];
#pragma unroll
            for (int h = 0; h < 2; h++) {
#pragma unroll
                for (int ar = 0; ar < 4; ar++) {
                    uint32_t addr = aBase +
                        (uint32_t)(((h * 128 + wm + ar * 16 + lr) * SPITCH + ks + lc) * 2);
                    ldsm4(fA[h][ar], addr);
                }
#pragma unroll
                for (int bp = 0; bp < 2; bp++) {
                    uint32_t addr = bBase +
                        (uint32_t)(((h * 128 + wn + bp * 16 + lr) * SPITCH + ks + lc) * 2);
                    ldsm4(fB[h][bp], addr);
                }
            }
#pragma unroll
            for (int ar = 0; ar < 4; ar++)
#pragma unroll
            for (int bn = 0; bn < 4; bn++) {
                int bp = bn >> 1, sel = bn & 1;
                uint32_t b0h = fB[0][bp][sel], b1h = fB[0][bp][2 + sel];
                uint32_t b0l = fB[1][bp][sel], b1l = fB[1][bp][2 + sel];
                mma16816(acc[ar][bn], fA[0][ar], b0h, b1h);
                mma16816(acc[ar][bn], fA[0][ar], b0l, b1l);
                mma16816(acc[ar][bn], fA[1][ar], b0h, b1h);
            }
        }
        if (more) {
            asm volatile("cp.async.wait_group 0;" ::: "memory");
            __syncthreads();
        }
    }

#pragma unroll
    for (int ar = 0; ar < 4; ar++) {
        int r0 = row0 + wm + ar * 16 + g;
        float bs0 = bias ? bias[r0]     : 0.0f;
        float bs8 = bias ? bias[r0 + 8] : 0.0f;
        float sumA = 0.0f, sumB = 0.0f;     // EPI3 row-sum partials
#pragma unroll
        for (int bn = 0; bn < 4; bn++) {
            int c0 = col0 + wn + bn * 8 + 2 * tig;
            float v0 = acc[ar][bn][0] + bs0;
            float v1 = acc[ar][bn][1] + bs0;
            float v2 = acc[ar][bn][2] + bs8;
            float v3 = acc[ar][bn][3] + bs8;
            if (RELU) {
                v0 = fmaxf(v0, 0.f); v1 = fmaxf(v1, 0.f);
                v2 = fmaxf(v2, 0.f); v3 = fmaxf(v3, 0.f);
            }
            if (EPI == 0) {
                float* C = Cf + (size_t)b * sCb;
                *(float2*)&C[(size_t)r0 * ldc + c0]       = make_float2(v0, v1);
                *(float2*)&C[(size_t)(r0 + 8) * ldc + c0] = make_float2(v2, v3);
            } else if (EPI == 1) {
                unsigned short* Hc = Ch + (size_t)b * sCb;
                unsigned short* Lc = Cl + (size_t)b * sCb;
                unsigned short h0, l0, h1, l1, h2, l2, h3, l3;
                split_bf16(v0, h0, l0); split_bf16(v1, h1, l1);
                split_bf16(v2, h2, l2); split_bf16(v3, h3, l3);
                *(uint32_t*)&Hc[(size_t)r0 * ldc + c0]       = (uint32_t)h0 | ((uint32_t)h1 << 16);
                *(uint32_t*)&Lc[(size_t)r0 * ldc + c0]       = (uint32_t)l0 | ((uint32_t)l1 << 16);
                *(uint32_t*)&Hc[(size_t)(r0 + 8) * ldc + c0] = (uint32_t)h2 | ((uint32_t)h3 << 16);
                *(uint32_t*)&Lc[(size_t)(r0 + 8) * ldc + c0] = (uint32_t)l2 | ((uint32_t)l3 << 16);
            } else if (EPI == 2) {
                if (Zp) {
                    float i0 = 1.0f / Zp[(size_t)b * NN + c0];
                    float i1 = 1.0f / Zp[(size_t)b * NN + c0 + 1];
                    v0 *= i0; v1 *= i1; v2 *= i0; v3 *= i1;
                }
                unsigned short* Hc = Ch + (size_t)b * sCb;
                unsigned short* Lc = Cl + (size_t)b * sCb;
                unsigned short h, l;
                split_bf16(v0, h, l);
                Hc[(size_t)c0 * ldc + r0] = h;           Lc[(size_t)c0 * ldc + r0] = l;
                split_bf16(v1, h, l);
                Hc[(size_t)(c0 + 1) * ldc + r0] = h;     Lc[(size_t)(c0 + 1) * ldc + r0] = l;
                split_bf16(v2, h, l);
                Hc[(size_t)c0 * ldc + r0 + 8] = h;       Lc[(size_t)c0 * ldc + r0 + 8] = l;
                split_bf16(v3, h, l);
                Hc[(size_t)(c0 + 1) * ldc + r0 + 8] = h; Lc[(size_t)(c0 + 1) * ldc + r0 + 8] = l;
            } else {  // EPI 3: exp + split store + row-sum partials
                float e0 = __expf(v0), e1 = __expf(v1);
                float e2 = __expf(v2), e3 = __expf(v3);
                sumA += e0 + e1;
                sumB += e2 + e3;
                unsigned short h0, l0, h1, l1, h2, l2, h3, l3;
                split_bf16(e0, h0, l0); split_bf16(e1, h1, l1);
                split_bf16(e2, h2, l2); split_bf16(e3, h3, l3);
                unsigned short* Hc = Ch + (size_t)b * sCb;
                unsigned short* Lc = Cl + (size_t)b * sCb;
                *(uint32_t*)&Hc[(size_t)r0 * ldc + c0]       = (uint32_t)h0 | ((uint32_t)h1 << 16);
                *(uint32_t*)&Lc[(size_t)r0 * ldc + c0]       = (uint32_t)l0 | ((uint32_t)l1 << 16);
                *(uint32_t*)&Hc[(size_t)(r0 + 8) * ldc + c0] = (uint32_t)h2 | ((uint32_t)h3 << 16);
                *(uint32_t*)&Lc[(size_t)(r0 + 8) * ldc + c0] = (uint32_t)l2 | ((uint32_t)l3 << 16);
            }
        }
        if (EPI == 3) {
            sumA += __shfl_xor_sync(0xffffffffu, sumA, 1);
            sumA += __shfl_xor_sync(0xffffffffu, sumA, 2);
            sumB += __shfl_xor_sync(0xffffffffu, sumB, 1);
            sumB += __shfl_xor_sync(0xffffffffu, sumB, 2);
            if (tig == 0) {
                atomicAdd(&Zp[(size_t)b * NN + r0], sumA);
                atomicAdd(&Zp[(size_t)b * NN + r0 + 8], sumB);
            }
        }
    }
}

// ---------------------------------------------------------------------------
extern "C" void kernel_launch(void* const* d_in, const int* in_sizes, int n_in,
                              void* d_out, int out_size) {
    const float* x_q  = (const float*)d_in[0];
    const float* x_kv = (const float*)d_in[1];
    const float* Wq = (const float*)d_in[2];
    const float* bq = (const float*)d_in[3];
    const float* Wk = (const float*)d_in[4];
    const float* bk = (const float*)d_in[5];
    const float* Wv = (const float*)d_in[6];
    const float* bv = (const float*)d_in[7];
    const float* W1 = (const float*)d_in[8];
    const float* b1 = (const float*)d_in[9];
    const float* W2 = (const float*)d_in[10];
    const float* b2 = (const float*)d_in[11];
    float* out = (float*)d_out;

    bf16 *xqt_h, *xqt_l, *xkt_h, *xkt_l, *w_h, *w_l;
    bf16 *qt_h, *qt_l, *kt_h, *kt_l, *v_h, *v_l;
    bf16 *ah, *al, *avt_h, *avt_l, *ht_h, *ht_l;
    float* pz;
    cudaGetSymbolAddress((void**)&xqt_h, g_xqt_h);
    cudaGetSymbolAddress((void**)&xqt_l, g_xqt_l);
    cudaGetSymbolAddress((void**)&xkt_h, g_xkt_h);
    cudaGetSymbolAddress((void**)&xkt_l, g_xkt_l);
    cudaGetSymbolAddress((void**)&w_h,   g_w_h);
    cudaGetSymbolAddress((void**)&w_l,   g_w_l);
    cudaGetSymbolAddress((void**)&qt_h,  g_qt_h);
    cudaGetSymbolAddress((void**)&qt_l,  g_qt_l);
    cudaGetSymbolAddress((void**)&kt_h,  g_kt_h);
    cudaGetSymbolAddress((void**)&kt_l,  g_kt_l);
    cudaGetSymbolAddress((void**)&v_h,   g_v_h);
    cudaGetSymbolAddress((void**)&v_l,   g_v_l);
    cudaGetSymbolAddress((void**)&ah,    g_ah);
    cudaGetSymbolAddress((void**)&al,    g_al);
    cudaGetSymbolAddress((void**)&pz,    g_z);
    cudaGetSymbolAddress((void**)&avt_h, g_avt_h);
    cudaGetSymbolAddress((void**)&avt_l, g_avt_l);
    cudaGetSymbolAddress((void**)&ht_h,  g_ht_h);
    cudaGetSymbolAddress((void**)&ht_l,  g_ht_l);

    cudaFuncSetAttribute(mma_gemm<0, false>, cudaFuncAttributeMaxDynamicSharedMemorySize, SMEM_TOTAL_BYTES);
    cudaFuncSetAttribute(mma_gemm<1, false>, cudaFuncAttributeMaxDynamicSharedMemorySize, SMEM_TOTAL_BYTES);
    cudaFuncSetAttribute(mma_gemm<2, false>, cudaFuncAttributeMaxDynamicSharedMemorySize, SMEM_TOTAL_BYTES);
    cudaFuncSetAttribute(mma_gemm<2, true>,  cudaFuncAttributeMaxDynamicSharedMemorySize, SMEM_TOTAL_BYTES);
    cudaFuncSetAttribute(mma_gemm<3, false>, cudaFuncAttributeMaxDynamicSharedMemorySize, SMEM_TOTAL_BYTES);

    const int WSZ = CC * CC;

    dim3 tb(256);
    dim3 gT(NN / 32, CC / 32, 2 * BB);
    dim3 gProj(NN / 128, CC / 128, BB);       // (32, 2, 4)
    dim3 gScore(NN / 128, NN / 128, BB);      // (32, 32, 4)

    // 1. input split-transpose (merged) + weight splits (merged) + Z zero
    split_transpose2<<<gT, dim3(32, 8)>>>(x_q, x_kv,
        (unsigned short*)xqt_h, (unsigned short*)xqt_l,
        (unsigned short*)xkt_h, (unsigned short*)xkt_l);
    split_all<<<5 * WSZ / 256, 256>>>(Wq, Wk, Wv, W1, W2,
        (unsigned short*)w_h, (unsigned short*)w_l);
    zero_z<<<BB * NN / 256, 256>>>(pz);

    // 2. projections
    mma_gemm<2, false><<<gProj, tb, SMEM_TOTAL_BYTES>>>(
        w_h + 0 * WSZ, w_l + 0 * WSZ, 0, CC,
        xqt_h, xqt_l, (size_t)NN * CC, CC,
        nullptr, (unsigned short*)qt_h, (unsigned short*)qt_l,
        (size_t)NN * CC, CC, bq, nullptr, CC);
    mma_gemm<2, false><<<gProj, tb, SMEM_TOTAL_BYTES>>>(
        w_h + 1 * WSZ, w_l + 1 * WSZ, 0, CC,
        xkt_h, xkt_l, (size_t)NN * CC, CC,
        nullptr, (unsigned short*)kt_h, (unsigned short*)kt_l,
        (size_t)NN * CC, CC, bk, nullptr, CC);
    mma_gemm<1, false><<<gProj, tb, SMEM_TOTAL_BYTES>>>(
        w_h + 2 * WSZ, w_l + 2 * WSZ, 0, CC,
        xkt_h, xkt_l, (size_t)NN * CC, CC,
        nullptr, (unsigned short*)v_h, (unsigned short*)v_l,
        (size_t)CC * NN, NN, bv, nullptr, CC);

    // 3. scores + fused exp + row sums (no separate softmax pass)
    mma_gemm<3, false><<<gScore, tb, SMEM_TOTAL_BYTES>>>(
        qt_h, qt_l, (size_t)NN * CC, CC,
        kt_h, kt_l, (size_t)NN * CC, CC,
        nullptr, (unsigned short*)ah, (unsigned short*)al,
        (size_t)NN * NN, NN, nullptr, pz, CC);

    // 4. AV with fused 1/Z normalization: av_t[n][c]
    mma_gemm<2, false><<<gProj, tb, SMEM_TOTAL_BYTES>>>(
        v_h, v_l, (size_t)CC * NN, NN,
        ah, al, (size_t)NN * NN, NN,
        nullptr, (unsigned short*)avt_h, (unsigned short*)avt_l,
        (size_t)NN * CC, CC, nullptr, pz, NN);

    // 5. FFN1 (relu fused): hid_t[n][o]
    mma_gemm<2, true><<<gProj, tb, SMEM_TOTAL_BYTES>>>(
        w_h + 3 * WSZ, w_l + 3 * WSZ, 0, CC,
        avt_h, avt_l, (size_t)NN * CC, CC,
        nullptr, (unsigned short*)ht_h, (unsigned short*)ht_l,
        (size_t)NN * CC, CC, b1, nullptr, CC);

    // 6. FFN2: fp32 out [o][n]
    mma_gemm<0, false><<<gProj, tb, SMEM_TOTAL_BYTES>>>(
        w_h + 4 * WSZ, w_l + 4 * WSZ, 0, CC,
        ht_h, ht_l, (size_t)NN * CC, CC,
        out, nullptr, nullptr, (size_t)CC * NN, NN, b2, nullptr, CC);
}

// round 10
// speedup vs baseline: 1.1045x; 1.0134x over previous
#include <cuda_runtime.h>
#include <cuda_bf16.h>
#include <math.h>
#include <stddef.h>
#include <stdint.h>

#define BB 4
#define CC 256
#define NN 4096

typedef __nv_bfloat16 bf16;
typedef unsigned short us;

// ---------------------------------------------------------------------------
// Scratch (__device__ globals; no allocation allowed)
// ---------------------------------------------------------------------------
__device__ __align__(16) bf16 g_xqt_h[(size_t)BB * NN * CC];  // x_q^T  [b][n][c]
__device__ __align__(16) bf16 g_xqt_l[(size_t)BB * NN * CC];
__device__ __align__(16) bf16 g_xkt_h[(size_t)BB * NN * CC];  // x_kv^T [b][n][c]
__device__ __align__(16) bf16 g_xkt_l[(size_t)BB * NN * CC];
__device__ __align__(16) bf16 g_w_h[5 * CC * CC];             // Wq,Wk,Wv,W1,W2 split
__device__ __align__(16) bf16 g_w_l[5 * CC * CC];
__device__ __align__(16) bf16 g_qt_h[(size_t)BB * NN * CC];   // q^T [b][n][c]
__device__ __align__(16) bf16 g_qt_l[(size_t)BB * NN * CC];
__device__ __align__(16) bf16 g_kt_h[(size_t)BB * NN * CC];   // k^T [b][m][c]
__device__ __align__(16) bf16 g_kt_l[(size_t)BB * NN * CC];
__device__ __align__(16) bf16 g_v_h[(size_t)BB * CC * NN];    // v   [b][c][m]
__device__ __align__(16) bf16 g_v_l[(size_t)BB * CC * NN];
__device__ __align__(16) bf16 g_ah[(size_t)BB * NN * NN];     // exp(S) hi [b][n][m]
__device__ __align__(16) bf16 g_al[(size_t)BB * NN * NN];     // exp(S) lo
__device__ __align__(16) float g_z[(size_t)BB * NN];          // row sums of exp(S)
__device__ __align__(16) bf16 g_avt_h[(size_t)BB * NN * CC];  // av^T [b][n][c]
__device__ __align__(16) bf16 g_avt_l[(size_t)BB * NN * CC];
__device__ __align__(16) bf16 g_ht_h[(size_t)BB * NN * CC];   // hid^T [b][n][c]
__device__ __align__(16) bf16 g_ht_l[(size_t)BB * NN * CC];

// ---------------------------------------------------------------------------
// helpers
// ---------------------------------------------------------------------------
__device__ __forceinline__ void split_bf16(float f, us& h, us& l) {
    bf16 hb = __float2bfloat16(f);
    float r = f - __bfloat162float(hb);
    bf16 lb = __float2bfloat16(r);
    h = __bfloat16_as_ushort(hb);
    l = __bfloat16_as_ushort(lb);
}

__device__ __forceinline__ void mma16816(float c[4],
                                         const uint32_t a[4],
                                         uint32_t b0, uint32_t b1) {
    asm volatile(
        "mma.sync.aligned.m16n8k16.row.col.f32.bf16.bf16.f32 "
        "{%0,%1,%2,%3}, {%4,%5,%6,%7}, {%8,%9}, {%0,%1,%2,%3};"
        : "+f"(c[0]), "+f"(c[1]), "+f"(c[2]), "+f"(c[3])
        : "r"(a[0]), "r"(a[1]), "r"(a[2]), "r"(a[3]), "r"(b0), "r"(b1));
}

__device__ __forceinline__ void ldsm4(uint32_t r[4], uint32_t addr) {
    asm volatile("ldmatrix.sync.aligned.m8n8.x4.shared.b16 {%0,%1,%2,%3}, [%4];"
                 : "=r"(r[0]), "=r"(r[1]), "=r"(r[2]), "=r"(r[3]) : "r"(addr));
}

__device__ __forceinline__ void cp16(uint32_t dst, const void* src) {
    asm volatile("cp.async.cg.shared.global [%0], [%1], 16;" :: "r"(dst), "l"(src));
}

// ---------------------------------------------------------------------------
// merged split-transpose: z<BB -> x_q, else x_kv.  [b][c][n] f32 -> [b][n][c] split
// ---------------------------------------------------------------------------
__global__ void split_transpose2(const float* __restrict__ Xq,
                                 const float* __restrict__ Xkv,
                                 us* __restrict__ Tqh, us* __restrict__ Tql,
                                 us* __restrict__ Tkh, us* __restrict__ Tkl) {
    __shared__ float tile[32][33];
    const int z  = blockIdx.z;
    const int b  = (z < BB) ? z : z - BB;
    const float* X = (z < BB) ? Xq : Xkv;
    us* Th = ((z < BB) ? Tqh : Tkh) + (size_t)b * NN * CC;
    us* Tl = ((z < BB) ? Tql : Tkl) + (size_t)b * NN * CC;

    const int c0 = blockIdx.y * 32;
    const int n0 = blockIdx.x * 32;
    const float* Xb = X + (size_t)b * CC * NN;
    const int tx = threadIdx.x, ty = threadIdx.y;

#pragma unroll
    for (int i = 0; i < 4; i++)
        tile[ty + 8 * i][tx] = Xb[(size_t)(c0 + ty + 8 * i) * NN + n0 + tx];
    __syncthreads();

#pragma unroll
    for (int i = 0; i < 4; i++) {
        float v = tile[tx][ty + 8 * i];
        us h, l;
        split_bf16(v, h, l);
        size_t off = (size_t)(n0 + ty + 8 * i) * CC + c0 + tx;
        Th[off] = h;
        Tl[off] = l;
    }
}

// ---------------------------------------------------------------------------
// merged weight split (5 matrices) + Z zeroing
// ---------------------------------------------------------------------------
__global__ void split_all(const float* __restrict__ W0, const float* __restrict__ W1,
                          const float* __restrict__ W2, const float* __restrict__ W3,
                          const float* __restrict__ W4,
                          us* __restrict__ Wh, us* __restrict__ Wl,
                          float* __restrict__ Z) {
    int i = blockIdx.x * blockDim.x + threadIdx.x;
    int which = i >> 16;           // CC*CC = 65536
    int off   = i & 65535;
    const float* src = (which == 0) ? W0 : (which == 1) ? W1 :
                       (which == 2) ? W2 : (which == 3) ? W3 : W4;
    us h, l;
    split_bf16(src[off], h, l);
    Wh[i] = h;
    Wl[i] = l;
    if (i < BB * NN) Z[i] = 0.0f;
}

// ---------------------------------------------------------------------------
// Shared HMMA mainloop: block 128x128, warp 64x32, 3-term bf16 split,
// cp.async double-buffered, hoisted copy addressing.
// ---------------------------------------------------------------------------
#define BKC 32
#define SPITCH 40
#define ST_ELEMS (2 * 128 * SPITCH)
#define ST_BYTES (ST_ELEMS * 2)
#define B_OFF_BYTES (2 * ST_BYTES)
#define SMEM_TOTAL_BYTES (4 * ST_BYTES)

extern __shared__ __align__(16) bf16 smem_mma[];

__device__ __forceinline__ void gemm_mainloop(
    const bf16* __restrict__ Ah, const bf16* __restrict__ Al, int lda,
    const bf16* __restrict__ Bh, const bf16* __restrict__ Bl, int ldb,
    int row0, int col0, int Ktot, uint32_t smem_u32, float acc[4][4][4]) {
    const int tid  = threadIdx.x;
    const int w    = tid >> 5, lane = tid & 31;
    const int wm   = (w & 1) * 64;
    const int wn   = (w >> 1) * 32;
    const int lr   = lane & 15;
    const int lc   = (lane >> 4) * 8;

    // hoisted per-thread copy descriptors (i -> fixed operand, fixed offsets)
    const bf16* srcs[8];
    uint32_t dsts[8];
#pragma unroll
    for (int i = 0; i < 8; i++) {
        int idx = tid + i * 256;
        int ab = idx >> 10, h = (idx >> 9) & 1;
        int r  = (idx >> 2) & 127, ch = idx & 3;
        const bf16* base = ab ? (h ? Bl : Bh) : (h ? Al : Ah);
        int ld = ab ? ldb : lda;
        int rr = (ab ? col0 : row0) + r;
        srcs[i] = base + (size_t)rr * ld + ch * 8;
        dsts[i] = (uint32_t)(((h * 128 + r) * SPITCH + ch * 8) * 2) +
                  (ab ? (uint32_t)B_OFF_BYTES : 0u);
    }

    auto issue_copy = [&](int k0, int st) {
        uint32_t sb = smem_u32 + st * ST_BYTES;
#pragma unroll
        for (int i = 0; i < 8; i++) cp16(sb + dsts[i], srcs[i] + k0);
        asm volatile("cp.async.commit_group;" ::: "memory");
    };

    issue_copy(0, 0);
    asm volatile("cp.async.wait_group 0;" ::: "memory");
    __syncthreads();

    const int nstep = Ktot / BKC;
    for (int s = 0; s < nstep; s++) {
        int st = s & 1;
        bool more = (s + 1) < nstep;
        if (more) issue_copy((s + 1) * BKC, st ^ 1);

        uint32_t aBase = smem_u32 + st * ST_BYTES;
        uint32_t bBase = aBase + B_OFF_BYTES;

#pragma unroll
        for (int ks = 0; ks < BKC; ks += 16) {
            uint32_t fA[2][4][4];
            uint32_t fB[2][2][4];
#pragma unroll
            for (int h = 0; h < 2; h++) {
#pragma unroll
                for (int ar = 0; ar < 4; ar++) {
                    uint32_t addr = aBase +
                        (uint32_t)(((h * 128 + wm + ar * 16 + lr) * SPITCH + ks + lc) * 2);
                    ldsm4(fA[h][ar], addr);
                }
#pragma unroll
                for (int bp = 0; bp < 2; bp++) {
                    uint32_t addr = bBase +
                        (uint32_t)(((h * 128 + wn + bp * 16 + lr) * SPITCH + ks + lc) * 2);
                    ldsm4(fB[h][bp], addr);
                }
            }
#pragma unroll
            for (int ar = 0; ar < 4; ar++)
#pragma unroll
            for (int bn = 0; bn < 4; bn++) {
                int bp = bn >> 1, sel = bn & 1;
                uint32_t b0h = fB[0][bp][sel], b1h = fB[0][bp][2 + sel];
                uint32_t b0l = fB[1][bp][sel], b1l = fB[1][bp][2 + sel];
                mma16816(acc[ar][bn], fA[0][ar], b0h, b1h);
                mma16816(acc[ar][bn], fA[0][ar], b0l, b1l);
                mma16816(acc[ar][bn], fA[1][ar], b0h, b1h);
            }
        }
        if (more) {
            asm volatile("cp.async.wait_group 0;" ::: "memory");
            __syncthreads();
        }
    }
}

// epilogue helpers ------------------------------------------------------------
__device__ __forceinline__ void epi_split_T(float v0, float v1, float v2, float v3,
                                            us* Hc, us* Lc, int ldc, int r0, int c0) {
    us h, l;
    split_bf16(v0, h, l);
    Hc[(size_t)c0 * ldc + r0] = h;           Lc[(size_t)c0 * ldc + r0] = l;
    split_bf16(v1, h, l);
    Hc[(size_t)(c0 + 1) * ldc + r0] = h;     Lc[(size_t)(c0 + 1) * ldc + r0] = l;
    split_bf16(v2, h, l);
    Hc[(size_t)c0 * ldc + r0 + 8] = h;       Lc[(size_t)c0 * ldc + r0 + 8] = l;
    split_bf16(v3, h, l);
    Hc[(size_t)(c0 + 1) * ldc + r0 + 8] = h; Lc[(size_t)(c0 + 1) * ldc + r0 + 8] = l;
}

__device__ __forceinline__ void epi_split_nat(float v0, float v1, float v2, float v3,
                                              us* Hc, us* Lc, int ldc, int r0, int c0) {
    us h0, l0, h1, l1, h2, l2, h3, l3;
    split_bf16(v0, h0, l0); split_bf16(v1, h1, l1);
    split_bf16(v2, h2, l2); split_bf16(v3, h3, l3);
    *(uint32_t*)&Hc[(size_t)r0 * ldc + c0]       = (uint32_t)h0 | ((uint32_t)h1 << 16);
    *(uint32_t*)&Lc[(size_t)r0 * ldc + c0]       = (uint32_t)l0 | ((uint32_t)l1 << 16);
    *(uint32_t*)&Hc[(size_t)(r0 + 8) * ldc + c0] = (uint32_t)h2 | ((uint32_t)h3 << 16);
    *(uint32_t*)&Lc[(size_t)(r0 + 8) * ldc + c0] = (uint32_t)l2 | ((uint32_t)l3 << 16);
}

// ---------------------------------------------------------------------------
// Generic GEMM kernel (scores/AV/FFN):
// EPI 0: fp32 [row][col] (+bias, opt relu)
// EPI 2: split bf16 transposed [col][row] (+bias, opt relu, opt 1/Z[col])
// EPI 3: exp() -> split bf16 [row][col] + atomic row sums into Zp
// ---------------------------------------------------------------------------
template <int EPI, bool RELU>
__global__ __launch_bounds__(256)
void mma_gemm(const bf16* __restrict__ Ah, const bf16* __restrict__ Al,
              size_t sAb, int lda,
              const bf16* __restrict__ Bh, const bf16* __restrict__ Bl,
              size_t sBb, int ldb,
              float* __restrict__ Cf,
              us* __restrict__ Ch, us* __restrict__ Cl,
              size_t sCb, int ldc,
              const float* __restrict__ bias, float* __restrict__ Zp, int Ktot) {
    const int b    = blockIdx.z;
    const int row0 = blockIdx.y * 128;
    const int col0 = blockIdx.x * 128;

    uint32_t smem_u32;
    asm("{ .reg .u64 t; cvta.to.shared.u64 t, %1; cvt.u32.u64 %0, t; }"
        : "=r"(smem_u32) : "l"(smem_mma));

    float acc[4][4][4] = {};
    gemm_mainloop(Ah + (size_t)b * sAb, Al + (size_t)b * sAb, lda,
                  Bh + (size_t)b * sBb, Bl + (size_t)b * sBb, ldb,
                  row0, col0, Ktot, smem_u32, acc);

    const int tid  = threadIdx.x;
    const int w    = tid >> 5, lane = tid & 31;
    const int g    = lane >> 2, tig = lane & 3;
    const int wm   = (w & 1) * 64;
    const int wn   = (w >> 1) * 32;

#pragma unroll
    for (int ar = 0; ar < 4; ar++) {
        int r0 = row0 + wm + ar * 16 + g;
        float bs0 = bias ? bias[r0]     : 0.0f;
        float bs8 = bias ? bias[r0 + 8] : 0.0f;
        float sumA = 0.0f, sumB = 0.0f;
#pragma unroll
        for (int bn = 0; bn < 4; bn++) {
            int c0 = col0 + wn + bn * 8 + 2 * tig;
            float v0 = acc[ar][bn][0] + bs0;
            float v1 = acc[ar][bn][1] + bs0;
            float v2 = acc[ar][bn][2] + bs8;
            float v3 = acc[ar][bn][3] + bs8;
            if (RELU) {
                v0 = fmaxf(v0, 0.f); v1 = fmaxf(v1, 0.f);
                v2 = fmaxf(v2, 0.f); v3 = fmaxf(v3, 0.f);
            }
            if (EPI == 0) {
                float* C = Cf + (size_t)b * sCb;
                *(float2*)&C[(size_t)r0 * ldc + c0]       = make_float2(v0, v1);
                *(float2*)&C[(size_t)(r0 + 8) * ldc + c0] = make_float2(v2, v3);
            } else if (EPI == 2) {
                if (Zp) {
                    float i0 = 1.0f / Zp[(size_t)b * NN + c0];
                    float i1 = 1.0f / Zp[(size_t)b * NN + c0 + 1];
                    v0 *= i0; v1 *= i1; v2 *= i0; v3 *= i1;
                }
                epi_split_T(v0, v1, v2, v3, Ch + (size_t)b * sCb, Cl + (size_t)b * sCb,
                            ldc, r0, c0);
            } else {  // EPI 3
                float e0 = __expf(v0), e1 = __expf(v1);
                float e2 = __expf(v2), e3 = __expf(v3);
                sumA += e0 + e1;
                sumB += e2 + e3;
                epi_split_nat(e0, e1, e2, e3, Ch + (size_t)b * sCb, Cl + (size_t)b * sCb,
                              ldc, r0, c0);
            }
        }
        if (EPI == 3) {
            sumA += __shfl_xor_sync(0xffffffffu, sumA, 1);
            sumA += __shfl_xor_sync(0xffffffffu, sumA, 2);
            sumB += __shfl_xor_sync(0xffffffffu, sumB, 1);
            sumB += __shfl_xor_sync(0xffffffffu, sumB, 2);
            if (tig == 0) {
                atomicAdd(&Zp[(size_t)b * NN + r0], sumA);
                atomicAdd(&Zp[(size_t)b * NN + r0 + 8], sumB);
            }
        }
    }
}

// ---------------------------------------------------------------------------
// Merged Q/K/V projection kernel: blockIdx.z encodes which*4 + b.
// Q,K -> transposed split ([n][c]); V -> natural split ([c][m]).
// ---------------------------------------------------------------------------
__global__ __launch_bounds__(256)
void proj_qkv(const bf16* __restrict__ w_h, const bf16* __restrict__ w_l,
              const bf16* __restrict__ xqt_h, const bf16* __restrict__ xqt_l,
              const bf16* __restrict__ xkt_h, const bf16* __restrict__ xkt_l,
              const float* __restrict__ bq, const float* __restrict__ bk,
              const float* __restrict__ bv,
              us* __restrict__ qt_h, us* __restrict__ qt_l,
              us* __restrict__ kt_h, us* __restrict__ kt_l,
              us* __restrict__ v_h, us* __restrict__ v_l) {
    const int z     = blockIdx.z;
    const int which = z >> 2;
    const int b     = z & 3;
    const int WSZ   = CC * CC;

    const bf16* Ah = w_h + which * WSZ;
    const bf16* Al = w_l + which * WSZ;
    const bf16* Bh = ((which == 0) ? xqt_h : xkt_h) + (size_t)b * NN * CC;
    const bf16* Bl = ((which == 0) ? xqt_l : xkt_l) + (size_t)b * NN * CC;
    const float* bias = (which == 0) ? bq : (which == 1) ? bk : bv;

    const int row0 = blockIdx.y * 128;
    const int col0 = blockIdx.x * 128;

    uint32_t smem_u32;
    asm("{ .reg .u64 t; cvta.to.shared.u64 t, %1; cvt.u32.u64 %0, t; }"
        : "=r"(smem_u32) : "l"(smem_mma));

    float acc[4][4][4] = {};
    gemm_mainloop(Ah, Al, CC, Bh, Bl, CC, row0, col0, CC, smem_u32, acc);

    const int tid  = threadIdx.x;
    const int w    = tid >> 5, lane = tid & 31;
    const int g    = lane >> 2, tig = lane & 3;
    const int wm   = (w & 1) * 64;
    const int wn   = (w >> 1) * 32;

    us *Hc, *Lc;
    int ldc;
    if (which == 0)      { Hc = qt_h + (size_t)b * NN * CC; Lc = qt_l + (size_t)b * NN * CC; ldc = CC; }
    else if (which == 1) { Hc = kt_h + (size_t)b * NN * CC; Lc = kt_l + (size_t)b * NN * CC; ldc = CC; }
    else                 { Hc = v_h  + (size_t)b * CC * NN; Lc = v_l  + (size_t)b * CC * NN; ldc = NN; }

#pragma unroll
    for (int ar = 0; ar < 4; ar++) {
        int r0 = row0 + wm + ar * 16 + g;
        float bs0 = bias[r0];
        float bs8 = bias[r0 + 8];
#pragma unroll
        for (int bn = 0; bn < 4; bn++) {
            int c0 = col0 + wn + bn * 8 + 2 * tig;
            float v0 = acc[ar][bn][0] + bs0;
            float v1 = acc[ar][bn][1] + bs0;
            float v2 = acc[ar][bn][2] + bs8;
            float v3 = acc[ar][bn][3] + bs8;
            if (which < 2) epi_split_T(v0, v1, v2, v3, Hc, Lc, ldc, r0, c0);
            else           epi_split_nat(v0, v1, v2, v3, Hc, Lc, ldc, r0, c0);
        }
    }
}

// ---------------------------------------------------------------------------
extern "C" void kernel_launch(void* const* d_in, const int* in_sizes, int n_in,
                              void* d_out, int out_size) {
    const float* x_q  = (const float*)d_in[0];
    const float* x_kv = (const float*)d_in[1];
    const float* Wq = (const float*)d_in[2];
    const float* bq = (const float*)d_in[3];
    const float* Wk = (const float*)d_in[4];
    const float* bk = (const float*)d_in[5];
    const float* Wv = (const float*)d_in[6];
    const float* bv = (const float*)d_in[7];
    const float* W1 = (const float*)d_in[8];
    const float* b1 = (const float*)d_in[9];
    const float* W2 = (const float*)d_in[10];
    const float* b2 = (const float*)d_in[11];
    float* out = (float*)d_out;

    bf16 *xqt_h, *xqt_l, *xkt_h, *xkt_l, *w_h, *w_l;
    bf16 *qt_h, *qt_l, *kt_h, *kt_l, *v_h, *v_l;
    bf16 *ah, *al, *avt_h, *avt_l, *ht_h, *ht_l;
    float* pz;
    cudaGetSymbolAddress((void**)&xqt_h, g_xqt_h);
    cudaGetSymbolAddress((void**)&xqt_l, g_xqt_l);
    cudaGetSymbolAddress((void**)&xkt_h, g_xkt_h);
    cudaGetSymbolAddress((void**)&xkt_l, g_xkt_l);
    cudaGetSymbolAddress((void**)&w_h,   g_w_h);
    cudaGetSymbolAddress((void**)&w_l,   g_w_l);
    cudaGetSymbolAddress((void**)&qt_h,  g_qt_h);
    cudaGetSymbolAddress((void**)&qt_l,  g_qt_l);
    cudaGetSymbolAddress((void**)&kt_h,  g_kt_h);
    cudaGetSymbolAddress((void**)&kt_l,  g_kt_l);
    cudaGetSymbolAddress((void**)&v_h,   g_v_h);
    cudaGetSymbolAddress((void**)&v_l,   g_v_l);
    cudaGetSymbolAddress((void**)&ah,    g_ah);
    cudaGetSymbolAddress((void**)&al,    g_al);
    cudaGetSymbolAddress((void**)&pz,    g_z);
    cudaGetSymbolAddress((void**)&avt_h, g_avt_h);
    cudaGetSymbolAddress((void**)&avt_l, g_avt_l);
    cudaGetSymbolAddress((void**)&ht_h,  g_ht_h);
    cudaGetSymbolAddress((void**)&ht_l,  g_ht_l);

    cudaFuncSetAttribute(mma_gemm<0, false>, cudaFuncAttributeMaxDynamicSharedMemorySize, SMEM_TOTAL_BYTES);
    cudaFuncSetAttribute(mma_gemm<2, false>, cudaFuncAttributeMaxDynamicSharedMemorySize, SMEM_TOTAL_BYTES);
    cudaFuncSetAttribute(mma_gemm<2, true>,  cudaFuncAttributeMaxDynamicSharedMemorySize, SMEM_TOTAL_BYTES);
    cudaFuncSetAttribute(mma_gemm<3, false>, cudaFuncAttributeMaxDynamicSharedMemorySize, SMEM_TOTAL_BYTES);
    cudaFuncSetAttribute(proj_qkv, cudaFuncAttributeMaxDynamicSharedMemorySize, SMEM_TOTAL_BYTES);

    const int WSZ = CC * CC;

    dim3 tb(256);
    dim3 gT(NN / 32, CC / 32, 2 * BB);
    dim3 gQKV(NN / 128, CC / 128, 3 * BB);    // (32, 2, 12)
    dim3 gProj(NN / 128, CC / 128, BB);       // (32, 2, 4)
    dim3 gScore(NN / 128, NN / 128, BB);      // (32, 32, 4)

    // 1. input split-transpose (merged) + weight splits (merged, + Z zero)
    split_transpose2<<<gT, dim3(32, 8)>>>(x_q, x_kv, (us*)xqt_h, (us*)xqt_l,
                                          (us*)xkt_h, (us*)xkt_l);
    split_all<<<5 * WSZ / 256, 256>>>(Wq, Wk, Wv, W1, W2, (us*)w_h, (us*)w_l, pz);

    // 2. all three projections in one launch
    proj_qkv<<<gQKV, tb, SMEM_TOTAL_BYTES>>>(
        w_h, w_l, xqt_h, xqt_l, xkt_h, xkt_l, bq, bk, bv,
        (us*)qt_h, (us*)qt_l, (us*)kt_h, (us*)kt_l, (us*)v_h, (us*)v_l);

    // 3. scores + fused exp + row sums
    mma_gemm<3, false><<<gScore, tb, SMEM_TOTAL_BYTES>>>(
        qt_h, qt_l, (size_t)NN * CC, CC,
        kt_h, kt_l, (size_t)NN * CC, CC,
        nullptr, (us*)ah, (us*)al,
        (size_t)NN * NN, NN, nullptr, pz, CC);

    // 4. AV with fused 1/Z normalization: av_t[n][c]
    mma_gemm<2, false><<<gProj, tb, SMEM_TOTAL_BYTES>>>(
        v_h, v_l, (size_t)CC * NN, NN,
        ah, al, (size_t)NN * NN, NN,
        nullptr, (us*)avt_h, (us*)avt_l,
        (size_t)NN * CC, CC, nullptr, pz, NN);

    // 5. FFN1 (relu fused): hid_t[n][o]
    mma_gemm<2, true><<<gProj, tb, SMEM_TOTAL_BYTES>>>(
        w_h + 3 * WSZ, w_l + 3 * WSZ, 0, CC,
        avt_h, avt_l, (size_t)NN * CC, CC,
        nullptr, (us*)ht_h, (us*)ht_l,
        (size_t)NN * CC, CC, b1, nullptr, CC);

    // 6. FFN2: fp32 out [o][n]
    mma_gemm<0, false><<<gProj, tb, SMEM_TOTAL_BYTES>>>(
        w_h + 4 * WSZ, w_l + 4 * WSZ, 0, CC,
        ht_h, ht_l, (size_t)NN * CC, CC,
        out, nullptr, nullptr, (size_t)CC * NN, NN, b2, nullptr, CC);
}